// round 1
// baseline (speedup 1.0000x reference)
#include <cuda_runtime.h>
#include <cuda_bf16.h>

// Problem constants
#define B_   8
#define LQ_  512
#define LK_  512
#define D_   512
#define H_   128
#define M_   (B_ * LQ_)   // 4096 rows for each projection

// Scratch for projected Q and K (no cudaMalloc allowed)
__device__ float g_Q[M_ * H_];
__device__ float g_K[M_ * H_];

__device__ __forceinline__ float fast_tanh(float x) {
    float y;
    asm("tanh.approx.f32 %0, %1;" : "=f"(y) : "f"(x));
    return y;
}

// ---------------------------------------------------------------------------
// Projection GEMM: Y[m, h] = sum_d X[m, d] * W[d, h]
// M=4096, K=512, N=128.  BM=64, BN=128 (full), BK=16.
// 256 threads, thread tile 8x4. grid.x = 2 * (M/64): first half does Q, second K.
// ---------------------------------------------------------------------------
#define BM 64
#define BK 16
#define BN 128

__global__ __launch_bounds__(256) void proj_kernel(
    const float* __restrict__ qs, const float* __restrict__ ks,
    const float* __restrict__ Wq, const float* __restrict__ Wk)
{
    const int nb = M_ / BM;                 // 64 blocks per projection
    bool isK = (blockIdx.x >= nb);
    int bm = isK ? (blockIdx.x - nb) : blockIdx.x;
    const float* __restrict__ X = isK ? ks : qs;
    const float* __restrict__ W = isK ? Wk : Wq;
    float* __restrict__ Y = isK ? g_K : g_Q;

    __shared__ float As[BM][BK + 1];   // +1 pad: stores conflict-light, reads broadcast
    __shared__ float Bs[BK][BN];

    int tid = threadIdx.x;
    int tx = tid & 31;       // 0..31 -> col group (4 cols each)
    int ty = tid >> 5;       // 0..7  -> row group (8 rows each)

    float acc[8][4];
#pragma unroll
    for (int i = 0; i < 8; i++)
#pragma unroll
        for (int j = 0; j < 4; j++) acc[i][j] = 0.f;

    const float* Xb = X + (size_t)(bm * BM) * D_;

    for (int k0 = 0; k0 < D_; k0 += BK) {
        // Load A tile 64x16: 1024 floats = 256 float4, one per thread.
        {
            int r = tid >> 2, c4 = tid & 3;
            float4 v = *(const float4*)(Xb + r * D_ + k0 + c4 * 4);
            As[r][c4 * 4 + 0] = v.x;
            As[r][c4 * 4 + 1] = v.y;
            As[r][c4 * 4 + 2] = v.z;
            As[r][c4 * 4 + 3] = v.w;
        }
        // Load B tile 16x128: 2048 floats = 512 float4, two per thread.
#pragma unroll
        for (int i = 0; i < 2; i++) {
            int idx = tid + i * 256;
            int r = idx >> 5, c4 = idx & 31;
            float4 v = *(const float4*)(W + (size_t)(k0 + r) * BN + c4 * 4);
            *(float4*)(&Bs[r][c4 * 4]) = v;
        }
        __syncthreads();

#pragma unroll
        for (int kk = 0; kk < BK; ++kk) {
            float a[8];
#pragma unroll
            for (int i = 0; i < 8; i++) a[i] = As[ty * 8 + i][kk];  // warp broadcast
            float4 bv = *(const float4*)(&Bs[kk][tx * 4]);          // LDS.128 conflict-free
            float bb[4] = {bv.x, bv.y, bv.z, bv.w};
#pragma unroll
            for (int i = 0; i < 8; i++)
#pragma unroll
                for (int j = 0; j < 4; j++)
                    acc[i][j] = fmaf(a[i], bb[j], acc[i][j]);
        }
        __syncthreads();
    }

    // Write 64x128 tile: each thread 8 rows x 4 contiguous cols (float4 stores)
#pragma unroll
    for (int i = 0; i < 8; i++) {
        float4 v = make_float4(acc[i][0], acc[i][1], acc[i][2], acc[i][3]);
        *(float4*)(Y + (size_t)(bm * BM + ty * 8 + i) * H_ + tx * 4) = v;
    }
}

// ---------------------------------------------------------------------------
// Score kernel: out[b,q,k] = sum_h wv[h] * tanh(Q[b,q,h] + K[b,k,h])
// Block: 64 q-rows x 64 k-rows, 256 threads (16x16), thread tile 4x4.
// h processed in two halves of 64 so static shared stays under 48 KB.
// ---------------------------------------------------------------------------
#define TQ 64
#define TK 64

__global__ __launch_bounds__(256) void score_kernel(
    const float* __restrict__ wv, float* __restrict__ out)
{
    __shared__ float sq[TQ][65];   // pad 65: k-reads conflict-free, q-reads broadcast
    __shared__ float sk[TK][65];
    __shared__ float swv[H_];

    int b  = blockIdx.z;
    int q0 = blockIdx.y * TQ;
    int k0 = blockIdx.x * TK;

    const float* Qb = g_Q + (size_t)(b * LQ_ + q0) * H_;
    const float* Kb = g_K + (size_t)(b * LK_ + k0) * H_;

    int tid = threadIdx.x;
    if (tid < H_) swv[tid] = wv[tid];

    int tx = tid & 15;    // k group: ki = tx + 16*j
    int ty = tid >> 4;    // q group: qi = ty + 16*i

    float acc[4][4];
#pragma unroll
    for (int i = 0; i < 4; i++)
#pragma unroll
        for (int j = 0; j < 4; j++) acc[i][j] = 0.f;

#pragma unroll
    for (int half = 0; half < 2; ++half) {
        __syncthreads();   // also covers swv on first iteration
        // Load 64x64 sub-tiles of Q and K: 1024 float4 each, 4 per thread per tile
        for (int i = tid; i < 1024; i += 256) {
            int r = i >> 4, c4 = i & 15;
            float4 v = *(const float4*)(Qb + r * H_ + half * 64 + c4 * 4);
            float* dq = &sq[r][c4 * 4];
            dq[0] = v.x; dq[1] = v.y; dq[2] = v.z; dq[3] = v.w;
            float4 w = *(const float4*)(Kb + r * H_ + half * 64 + c4 * 4);
            float* dk = &sk[r][c4 * 4];
            dk[0] = w.x; dk[1] = w.y; dk[2] = w.z; dk[3] = w.w;
        }
        __syncthreads();

#pragma unroll 4
        for (int h = 0; h < 64; ++h) {
            float wvh = swv[half * 64 + h];
            float qv[4], kv[4];
#pragma unroll
            for (int i = 0; i < 4; i++) qv[i] = sq[ty + 16 * i][h];
#pragma unroll
            for (int j = 0; j < 4; j++) kv[j] = sk[tx + 16 * j][h];
#pragma unroll
            for (int i = 0; i < 4; i++)
#pragma unroll
                for (int j = 0; j < 4; j++)
                    acc[i][j] = fmaf(wvh, fast_tanh(qv[i] + kv[j]), acc[i][j]);
        }
    }

    float* ob = out + ((size_t)b * LQ_ + q0) * LK_ + k0;
#pragma unroll
    for (int i = 0; i < 4; i++)
#pragma unroll
        for (int j = 0; j < 4; j++)
            ob[(size_t)(ty + 16 * i) * LK_ + tx + 16 * j] = acc[i][j];
}

// ---------------------------------------------------------------------------

extern "C" void kernel_launch(void* const* d_in, const int* in_sizes, int n_in,
                              void* d_out, int out_size)
{
    const float* qs = (const float*)d_in[0];   // [8,512,512]
    const float* ks = (const float*)d_in[1];   // [8,512,512]
    const float* Wq = (const float*)d_in[2];   // [512,128]
    const float* Wk = (const float*)d_in[3];   // [512,128]
    const float* wv = (const float*)d_in[4];   // [128]
    float* out = (float*)d_out;                // [8,512,512]

    // Both projections in one launch: 128 blocks (Q blocks then K blocks)
    proj_kernel<<<2 * (M_ / BM), 256>>>(qs, ks, Wq, Wk);

    dim3 grid(LK_ / TK, LQ_ / TQ, B_);
    score_kernel<<<grid, 256>>>(wv, out);
}

// round 2
// speedup vs baseline: 1.0693x; 1.0693x over previous
#include <cuda_runtime.h>
#include <cuda_bf16.h>

// Problem constants
#define B_   8
#define LQ_  512
#define LK_  512
#define D_   512
#define H_   128
#define M_   (B_ * LQ_)   // 4096 rows for each projection

// Scratch for projected Q and K (no cudaMalloc allowed)
__device__ float g_Q[M_ * H_];
__device__ float g_K[M_ * H_];

__device__ __forceinline__ float fast_tanh(float x) {
    float y;
    asm("tanh.approx.f32 %0, %1;" : "=f"(y) : "f"(x));
    return y;
}

// ---------------------------------------------------------------------------
// Projection GEMM: Y[m, h] = sum_d X[m, d] * W[d, h]
// M=4096, K=512, N=128.  BM=64, BN=128 (full), BK=16.
// 256 threads, thread tile 8x4. grid.x = 2 * (M/64): first half does Q, second K.
// (At fp32 FMA roofline: ~35us. Leave unchanged.)
// ---------------------------------------------------------------------------
#define BM 64
#define BK 16
#define BN 128

__global__ __launch_bounds__(256) void proj_kernel(
    const float* __restrict__ qs, const float* __restrict__ ks,
    const float* __restrict__ Wq, const float* __restrict__ Wk)
{
    const int nb = M_ / BM;                 // 64 blocks per projection
    bool isK = (blockIdx.x >= nb);
    int bm = isK ? (blockIdx.x - nb) : blockIdx.x;
    const float* __restrict__ X = isK ? ks : qs;
    const float* __restrict__ W = isK ? Wk : Wq;
    float* __restrict__ Y = isK ? g_K : g_Q;

    __shared__ float As[BM][BK + 1];
    __shared__ float Bs[BK][BN];

    int tid = threadIdx.x;
    int tx = tid & 31;       // col group (4 cols each)
    int ty = tid >> 5;       // row group (8 rows each)

    float acc[8][4];
#pragma unroll
    for (int i = 0; i < 8; i++)
#pragma unroll
        for (int j = 0; j < 4; j++) acc[i][j] = 0.f;

    const float* Xb = X + (size_t)(bm * BM) * D_;

    for (int k0 = 0; k0 < D_; k0 += BK) {
        {
            int r = tid >> 2, c4 = tid & 3;
            float4 v = *(const float4*)(Xb + r * D_ + k0 + c4 * 4);
            As[r][c4 * 4 + 0] = v.x;
            As[r][c4 * 4 + 1] = v.y;
            As[r][c4 * 4 + 2] = v.z;
            As[r][c4 * 4 + 3] = v.w;
        }
#pragma unroll
        for (int i = 0; i < 2; i++) {
            int idx = tid + i * 256;
            int r = idx >> 5, c4 = idx & 31;
            float4 v = *(const float4*)(W + (size_t)(k0 + r) * BN + c4 * 4);
            *(float4*)(&Bs[r][c4 * 4]) = v;
        }
        __syncthreads();

#pragma unroll
        for (int kk = 0; kk < BK; ++kk) {
            float a[8];
#pragma unroll
            for (int i = 0; i < 8; i++) a[i] = As[ty * 8 + i][kk];
            float4 bv = *(const float4*)(&Bs[kk][tx * 4]);
            float bb[4] = {bv.x, bv.y, bv.z, bv.w};
#pragma unroll
            for (int i = 0; i < 8; i++)
#pragma unroll
                for (int j = 0; j < 4; j++)
                    acc[i][j] = fmaf(a[i], bb[j], acc[i][j]);
        }
        __syncthreads();
    }

#pragma unroll
    for (int i = 0; i < 8; i++) {
        float4 v = make_float4(acc[i][0], acc[i][1], acc[i][2], acc[i][3]);
        *(float4*)(Y + (size_t)(bm * BM + ty * 8 + i) * H_ + tx * 4) = v;
    }
}

// ---------------------------------------------------------------------------
// Score kernel: out[b,q,k] = sum_h wv[h] * tanh(Q[b,q,h] + K[b,k,h])
// Block: 32 q-rows x 64 k-rows, 256 threads (16x16), thread tile 2x4.
// 1024 blocks -> 6.92/SM -> per-SM block-count imbalance ~1%, vs 16% at 64x64.
// MUFU-bound: 8 tanh (64 SMSP-cyc) vs 16 fma-pipe instrs (32 cyc) per h-iter.
// ---------------------------------------------------------------------------
#define TQ 32
#define TK 64

__global__ __launch_bounds__(256) void score_kernel(
    const float* __restrict__ wv, float* __restrict__ out)
{
    __shared__ float sq[TQ][65];   // pad 65: conflict-free strided reads
    __shared__ float sk[TK][65];
    __shared__ float swv[H_];

    int b  = blockIdx.z;
    int q0 = blockIdx.y * TQ;
    int k0 = blockIdx.x * TK;

    const float* Qb = g_Q + (size_t)(b * LQ_ + q0) * H_;
    const float* Kb = g_K + (size_t)(b * LK_ + k0) * H_;

    int tid = threadIdx.x;
    if (tid < H_) swv[tid] = wv[tid];

    int tx = tid & 15;    // k group: ki = tx + 16*j  (j=0..3)
    int ty = tid >> 4;    // q group: qi = ty + 16*i  (i=0..1)

    float acc[2][4];
#pragma unroll
    for (int i = 0; i < 2; i++)
#pragma unroll
        for (int j = 0; j < 4; j++) acc[i][j] = 0.f;

#pragma unroll
    for (int half = 0; half < 2; ++half) {
        __syncthreads();   // also covers swv on first iteration
        // Q sub-tile 32x64: 512 float4 (2/thread); K sub-tile 64x64: 1024 float4 (4/thread)
        for (int i = tid; i < 512; i += 256) {
            int r = i >> 4, c4 = i & 15;
            float4 v = *(const float4*)(Qb + r * H_ + half * 64 + c4 * 4);
            float* dq = &sq[r][c4 * 4];
            dq[0] = v.x; dq[1] = v.y; dq[2] = v.z; dq[3] = v.w;
        }
        for (int i = tid; i < 1024; i += 256) {
            int r = i >> 4, c4 = i & 15;
            float4 w = *(const float4*)(Kb + r * H_ + half * 64 + c4 * 4);
            float* dk = &sk[r][c4 * 4];
            dk[0] = w.x; dk[1] = w.y; dk[2] = w.z; dk[3] = w.w;
        }
        __syncthreads();

#pragma unroll 4
        for (int h = 0; h < 64; ++h) {
            float wvh = swv[half * 64 + h];
            float qv[2], kv[4];
#pragma unroll
            for (int i = 0; i < 2; i++) qv[i] = sq[ty + 16 * i][h];
#pragma unroll
            for (int j = 0; j < 4; j++) kv[j] = sk[tx + 16 * j][h];
#pragma unroll
            for (int i = 0; i < 2; i++)
#pragma unroll
                for (int j = 0; j < 4; j++)
                    acc[i][j] = fmaf(wvh, fast_tanh(qv[i] + kv[j]), acc[i][j]);
        }
    }

    float* ob = out + ((size_t)b * LQ_ + q0) * LK_ + k0;
#pragma unroll
    for (int i = 0; i < 2; i++)
#pragma unroll
        for (int j = 0; j < 4; j++)
            ob[(size_t)(ty + 16 * i) * LK_ + tx + 16 * j] = acc[i][j];
}

// ---------------------------------------------------------------------------

extern "C" void kernel_launch(void* const* d_in, const int* in_sizes, int n_in,
                              void* d_out, int out_size)
{
    const float* qs = (const float*)d_in[0];   // [8,512,512]
    const float* ks = (const float*)d_in[1];   // [8,512,512]
    const float* Wq = (const float*)d_in[2];   // [512,128]
    const float* Wk = (const float*)d_in[3];   // [512,128]
    const float* wv = (const float*)d_in[4];   // [128]
    float* out = (float*)d_out;                // [8,512,512]

    proj_kernel<<<2 * (M_ / BM), 256>>>(qs, ks, Wq, Wk);

    dim3 grid(LK_ / TK, LQ_ / TQ, B_);
    score_kernel<<<grid, 256>>>(wv, out);
}

// round 3
// speedup vs baseline: 1.1148x; 1.0426x over previous
#include <cuda_runtime.h>
#include <cuda_bf16.h>

// Problem constants
#define B_   8
#define LQ_  512
#define LK_  512
#define D_   512
#define H_   128
#define M_   (B_ * LQ_)   // 4096 rows per projection

// Scratch for projected Q and K (no cudaMalloc allowed)
__device__ float g_Q[M_ * H_];
__device__ float g_K[M_ * H_];

__device__ __forceinline__ float fast_tanh(float x) {
    float y;
    asm("tanh.approx.f32 %0, %1;" : "=f"(y) : "f"(x));
    return y;
}

// Packed fp32x2 FMA (Blackwell FFMA2) — IEEE fp32 fused, bit-identical to fmaf.
__device__ __forceinline__ unsigned long long fma_f32x2(
    unsigned long long a, unsigned long long b, unsigned long long c) {
    unsigned long long d;
    asm("fma.rn.f32x2 %0, %1, %2, %3;" : "=l"(d) : "l"(a), "l"(b), "l"(c));
    return d;
}
__device__ __forceinline__ unsigned long long pack2(float lo, float hi) {
    unsigned long long p;
    asm("mov.b64 %0, {%1, %2};" : "=l"(p) : "f"(lo), "f"(hi));
    return p;
}
__device__ __forceinline__ void unpack2(unsigned long long p, float& lo, float& hi) {
    asm("mov.b64 {%0, %1}, %2;" : "=f"(lo), "=f"(hi) : "l"(p));
}

// ---------------------------------------------------------------------------
// Projection GEMM: Y[m, h] = sum_d X[m, d] * W[d, h]
// M=4096, K=512, N=128.  BM=64, BN=128, BK=16. 256 threads.
// Thread tile: 8 rows (4 packed f32x2 pairs) x 4 cols -> 16 FFMA2 per kk.
// As stored transposed [BK][BM+8] so row-pairs load as broadcast LDS.128.
// Register prefetch double-buffers the gmem tile loads.
// ---------------------------------------------------------------------------
#define BM 64
#define BK 16
#define BN 128
#define APAD 8   // As row stride 72 floats: 32B-aligned rows, broadcast reads

__global__ __launch_bounds__(256) void proj_kernel(
    const float* __restrict__ qs, const float* __restrict__ ks,
    const float* __restrict__ Wq, const float* __restrict__ Wk)
{
    const int nb = M_ / BM;                 // 64 blocks per projection
    bool isK = (blockIdx.x >= nb);
    int bm = isK ? (blockIdx.x - nb) : blockIdx.x;
    const float* __restrict__ X = isK ? ks : qs;
    const float* __restrict__ W = isK ? Wk : Wq;
    float* __restrict__ Y = isK ? g_K : g_Q;

    __shared__ float As[BK][BM + APAD];  // transposed: As[k][m]
    __shared__ float Bs[BK][BN];

    int tid = threadIdx.x;
    int tx = tid & 31;       // col group (4 cols)
    int ty = tid >> 5;       // row group (8 rows)

    // A-tile load mapping: row ar (m-dim), k-cols ac4*4..+3
    int ar  = tid >> 2;
    int ac4 = tid & 3;
    // B-tile load mapping: two float4 per thread
    int br  = tid >> 5;      // rows br and br+8 (k-dim)
    int bc4 = tid & 31;      // col group

    const float* Xp = X + (size_t)(bm * BM + ar) * D_ + ac4 * 4;
    const float* Wp0 = W + (size_t)br * BN + bc4 * 4;
    const float* Wp1 = W + (size_t)(br + 8) * BN + bc4 * 4;

    unsigned long long acc2[4][4];
#pragma unroll
    for (int i = 0; i < 4; i++)
#pragma unroll
        for (int j = 0; j < 4; j++) acc2[i][j] = 0ull;

    // Prefetch first tiles into registers
    float4 pa  = *(const float4*)(Xp);
    float4 pb0 = *(const float4*)(Wp0);
    float4 pb1 = *(const float4*)(Wp1);

    for (int k0 = 0; k0 < D_; k0 += BK) {
        // Stage prefetched tiles into shared
        As[ac4 * 4 + 0][ar] = pa.x;
        As[ac4 * 4 + 1][ar] = pa.y;
        As[ac4 * 4 + 2][ar] = pa.z;
        As[ac4 * 4 + 3][ar] = pa.w;
        *(float4*)(&Bs[br][bc4 * 4])     = pb0;
        *(float4*)(&Bs[br + 8][bc4 * 4]) = pb1;
        __syncthreads();

        // Prefetch next tiles (hidden under compute)
        if (k0 + BK < D_) {
            pa  = *(const float4*)(Xp + k0 + BK);
            pb0 = *(const float4*)(Wp0 + (size_t)(k0 + BK) * BN);
            pb1 = *(const float4*)(Wp1 + (size_t)(k0 + BK) * BN);
        }

#pragma unroll
        for (int kk = 0; kk < BK; ++kk) {
            // 4 packed row-pairs, broadcast LDS.128 (all lanes same address)
            ulonglong2 a01 = *(const ulonglong2*)(&As[kk][ty * 8]);
            ulonglong2 a23 = *(const ulonglong2*)(&As[kk][ty * 8 + 4]);
            unsigned long long ap[4] = {a01.x, a01.y, a23.x, a23.y};
            float4 bv = *(const float4*)(&Bs[kk][tx * 4]);
            unsigned long long bd[4] = {
                pack2(bv.x, bv.x), pack2(bv.y, bv.y),
                pack2(bv.z, bv.z), pack2(bv.w, bv.w)};
#pragma unroll
            for (int i = 0; i < 4; i++)
#pragma unroll
                for (int j = 0; j < 4; j++)
                    acc2[i][j] = fma_f32x2(ap[i], bd[j], acc2[i][j]);
        }
        __syncthreads();
    }

    // Epilogue: acc2[i][j] = (row ty*8+2i, col tx*4+j) in lo, (row +2i+1) in hi
#pragma unroll
    for (int i = 0; i < 4; i++) {
        float lo[4], hi[4];
#pragma unroll
        for (int j = 0; j < 4; j++) unpack2(acc2[i][j], lo[j], hi[j]);
        size_t r0 = (size_t)(bm * BM + ty * 8 + 2 * i) * H_ + tx * 4;
        *(float4*)(Y + r0)      = make_float4(lo[0], lo[1], lo[2], lo[3]);
        *(float4*)(Y + r0 + H_) = make_float4(hi[0], hi[1], hi[2], hi[3]);
    }
}

// ---------------------------------------------------------------------------
// Score kernel: out[b,q,k] = sum_h wv[h] * tanh(Q[b,q,h] + K[b,k,h])
// 32q x 64k tiles, 256 threads, thread tile 2x4. 1024 blocks (balanced).
// MUFU-bound at ~92% of roofline — unchanged this round.
// ---------------------------------------------------------------------------
#define TQ 32
#define TK 64

__global__ __launch_bounds__(256) void score_kernel(
    const float* __restrict__ wv, float* __restrict__ out)
{
    __shared__ float sq[TQ][65];
    __shared__ float sk[TK][65];
    __shared__ float swv[H_];

    int b  = blockIdx.z;
    int q0 = blockIdx.y * TQ;
    int k0 = blockIdx.x * TK;

    const float* Qb = g_Q + (size_t)(b * LQ_ + q0) * H_;
    const float* Kb = g_K + (size_t)(b * LK_ + k0) * H_;

    int tid = threadIdx.x;
    if (tid < H_) swv[tid] = wv[tid];

    int tx = tid & 15;
    int ty = tid >> 4;

    float acc[2][4];
#pragma unroll
    for (int i = 0; i < 2; i++)
#pragma unroll
        for (int j = 0; j < 4; j++) acc[i][j] = 0.f;

#pragma unroll
    for (int half = 0; half < 2; ++half) {
        __syncthreads();
        for (int i = tid; i < 512; i += 256) {
            int r = i >> 4, c4 = i & 15;
            float4 v = *(const float4*)(Qb + r * H_ + half * 64 + c4 * 4);
            float* dq = &sq[r][c4 * 4];
            dq[0] = v.x; dq[1] = v.y; dq[2] = v.z; dq[3] = v.w;
        }
        for (int i = tid; i < 1024; i += 256) {
            int r = i >> 4, c4 = i & 15;
            float4 w = *(const float4*)(Kb + r * H_ + half * 64 + c4 * 4);
            float* dk = &sk[r][c4 * 4];
            dk[0] = w.x; dk[1] = w.y; dk[2] = w.z; dk[3] = w.w;
        }
        __syncthreads();

#pragma unroll 4
        for (int h = 0; h < 64; ++h) {
            float wvh = swv[half * 64 + h];
            float qv[2], kv[4];
#pragma unroll
            for (int i = 0; i < 2; i++) qv[i] = sq[ty + 16 * i][h];
#pragma unroll
            for (int j = 0; j < 4; j++) kv[j] = sk[tx + 16 * j][h];
#pragma unroll
            for (int i = 0; i < 2; i++)
#pragma unroll
                for (int j = 0; j < 4; j++)
                    acc[i][j] = fmaf(wvh, fast_tanh(qv[i] + kv[j]), acc[i][j]);
        }
    }

    float* ob = out + ((size_t)b * LQ_ + q0) * LK_ + k0;
#pragma unroll
    for (int i = 0; i < 2; i++)
#pragma unroll
        for (int j = 0; j < 4; j++)
            ob[(size_t)(ty + 16 * i) * LK_ + tx + 16 * j] = acc[i][j];
}

// ---------------------------------------------------------------------------

extern "C" void kernel_launch(void* const* d_in, const int* in_sizes, int n_in,
                              void* d_out, int out_size)
{
    const float* qs = (const float*)d_in[0];   // [8,512,512]
    const float* ks = (const float*)d_in[1];   // [8,512,512]
    const float* Wq = (const float*)d_in[2];   // [512,128]
    const float* Wk = (const float*)d_in[3];   // [512,128]
    const float* wv = (const float*)d_in[4];   // [128]
    float* out = (float*)d_out;                // [8,512,512]

    proj_kernel<<<2 * (M_ / BM), 256>>>(qs, ks, Wq, Wk);

    dim3 grid(LK_ / TK, LQ_ / TQ, B_);
    score_kernel<<<grid, 256>>>(wv, out);
}